// round 1
// baseline (speedup 1.0000x reference)
#include <cuda_runtime.h>

#define B_  4
#define NXq 1024
#define NYk 1024
#define C_  768
#define H_  12
#define D_  64
#define NH  (B_*H_)   // 48

// ---------------- scratch (static device globals; no allocation) ----------------
__device__ float g_ynorm[B_*NYk*C_];            // 12.6 MB
__device__ float g_q    [B_*NXq*C_];            // 12.6 MB
__device__ float g_kv   [B_*NYk*2*C_];          // 25.2 MB
__device__ float g_attn [B_*NXq*C_];            // 12.6 MB
__device__ float g_S    [48*1024*1024];         // 201 MB  (scores -> then combined weights)

// ---------------- fused multiscale depthwise conv + LayerNorm ----------------
__global__ void __launch_bounds__(256) conv_ln_kernel(
    const float* __restrict__ y,
    const float* __restrict__ c1w, const float* __restrict__ c1b,
    const float* __restrict__ c2w, const float* __restrict__ c2b,
    const float* __restrict__ c3w, const float* __restrict__ c3b,
    const float* __restrict__ lnw, const float* __restrict__ lnb)
{
    int row = blockIdx.x;            // b*NY + ny
    int b  = row >> 10;
    int ny = row & 1023;
    const float* yb = y + (size_t)b * NYk * C_;
    int tid = threadIdx.x;

    float vals[3];
    float lsum = 0.f, lsq = 0.f;
    #pragma unroll
    for (int i = 0; i < 3; i++) {
        int c = tid + i * 256;
        // effective 7-tap depthwise kernel = conv3 + padded conv2 + padded conv1
        float w7[7];
        #pragma unroll
        for (int j = 0; j < 7; j++) w7[j] = c3w[c*7 + j];
        #pragma unroll
        for (int j = 0; j < 5; j++) w7[j+1] += c2w[c*5 + j];
        #pragma unroll
        for (int j = 0; j < 3; j++) w7[j+2] += c1w[c*3 + j];
        float acc = c1b[c] + c2b[c] + c3b[c];
        #pragma unroll
        for (int j = 0; j < 7; j++) {
            int nn = ny + j - 3;
            if (nn >= 0 && nn < NYk) acc += w7[j] * yb[(size_t)nn * C_ + c];
        }
        vals[i] = acc; lsum += acc; lsq += acc * acc;
    }

    __shared__ float s1[256], s2[256];
    s1[tid] = lsum; s2[tid] = lsq;
    __syncthreads();
    for (int s = 128; s > 0; s >>= 1) {
        if (tid < s) { s1[tid] += s1[tid+s]; s2[tid] += s2[tid+s]; }
        __syncthreads();
    }
    float mean = s1[0] * (1.0f / C_);
    float var  = s2[0] * (1.0f / C_) - mean * mean;
    float rstd = rsqrtf(var + 1e-5f);

    float* orow = g_ynorm + (size_t)row * C_;
    #pragma unroll
    for (int i = 0; i < 3; i++) {
        int c = tid + i * 256;
        orow[c] = (vals[i] - mean) * rstd * lnw[c] + lnb[c];
    }
}

// ---------------- generic NT SIMT GEMM:  C[m,n] = alpha * sum_k A[m,k]*B[n,k] ----------------
// 128x128 tile, BK=8, 256 threads, 8x8 per thread. Batched via blockIdx.z with
// two-level (zo = z/HH, zi = z%HH) offsets so (b,h) head slicing works.
template<int HASB, int HASR>
__global__ void __launch_bounds__(256) gemm_nt_128x128(
    const float* __restrict__ A, const float* __restrict__ Bm,
    float* __restrict__ Cm, const float* __restrict__ bias,
    const float* __restrict__ res,
    int K, int lda, int ldb, int ldc, float alpha,
    int HH, long long aO, long long aI, long long bO, long long bI,
    long long cO, long long cI)
{
    int z  = blockIdx.z;
    int zo = z / HH, zi = z - zo * HH;
    A  += zo * aO + zi * aI;
    Bm += zo * bO + zi * bI;
    Cm += zo * cO + zi * cI;
    const float* R = res;
    if (HASR) R += zo * cO + zi * cI;

    __shared__ float As[8][128];
    __shared__ float Bs[8][128];
    int tid = threadIdx.x;
    int tx = tid & 15, ty = tid >> 4;
    long long m0 = (long long)blockIdx.y * 128;
    long long n0 = (long long)blockIdx.x * 128;

    float acc[8][8];
    #pragma unroll
    for (int i = 0; i < 8; i++)
        #pragma unroll
        for (int j = 0; j < 8; j++) acc[i][j] = 0.f;

    int lrow = tid >> 1;
    int lcol = (tid & 1) * 4;
    const float* Aptr = A  + (m0 + lrow) * (long long)lda + lcol;
    const float* Bptr = Bm + (n0 + lrow) * (long long)ldb + lcol;

    for (int k0 = 0; k0 < K; k0 += 8) {
        float4 av = *(const float4*)(Aptr + k0);
        float4 bv = *(const float4*)(Bptr + k0);
        __syncthreads();
        As[lcol+0][lrow] = av.x; As[lcol+1][lrow] = av.y;
        As[lcol+2][lrow] = av.z; As[lcol+3][lrow] = av.w;
        Bs[lcol+0][lrow] = bv.x; Bs[lcol+1][lrow] = bv.y;
        Bs[lcol+2][lrow] = bv.z; Bs[lcol+3][lrow] = bv.w;
        __syncthreads();
        #pragma unroll
        for (int kk = 0; kk < 8; kk++) {
            float a[8], bb[8];
            #pragma unroll
            for (int i = 0; i < 8; i++) a[i]  = As[kk][ty*8 + i];
            #pragma unroll
            for (int j = 0; j < 8; j++) bb[j] = Bs[kk][tx*8 + j];
            #pragma unroll
            for (int i = 0; i < 8; i++)
                #pragma unroll
                for (int j = 0; j < 8; j++) acc[i][j] += a[i] * bb[j];
        }
    }

    #pragma unroll
    for (int i = 0; i < 8; i++) {
        long long m = m0 + ty*8 + i;
        #pragma unroll
        for (int j = 0; j < 8; j++) {
            long long n = n0 + tx*8 + j;
            float v = acc[i][j] * alpha;
            if (HASB) v += bias[n];
            if (HASR) v += R[m * ldc + n];
            Cm[m * ldc + n] = v;
        }
    }
}

// ---------------- NN SIMT GEMM for W@V:  C[m,n] = sum_k A[m,k]*B[k,n] ----------------
// 128x64 tile, BK=16, 256 threads, 8x4 per thread.
__global__ void __launch_bounds__(256) gemm_nn_128x64(
    const float* __restrict__ A, const float* __restrict__ Bm, float* __restrict__ Cm,
    int K, int lda, int ldb, int ldc, float alpha,
    int HH, long long aO, long long aI, long long bO, long long bI,
    long long cO, long long cI)
{
    int z  = blockIdx.z;
    int zo = z / HH, zi = z - zo * HH;
    A  += zo * aO + zi * aI;
    Bm += zo * bO + zi * bI;
    Cm += zo * cO + zi * cI;

    __shared__ float As[16][128];
    __shared__ float Bs[16][64];
    int tid = threadIdx.x;
    int tx = tid & 15, ty = tid >> 4;
    long long m0 = (long long)blockIdx.y * 128;
    long long n0 = (long long)blockIdx.x * 64;

    float acc[8][4];
    #pragma unroll
    for (int i = 0; i < 8; i++)
        #pragma unroll
        for (int j = 0; j < 4; j++) acc[i][j] = 0.f;

    int arow = tid >> 1, acol = (tid & 1) * 8;
    int brow = tid >> 4, bcol = (tid & 15) * 4;
    const float* Aptr = A  + (m0 + arow) * (long long)lda + acol;
    const float* Bptr = Bm + (long long)brow * ldb + n0 + bcol;

    for (int k0 = 0; k0 < K; k0 += 16) {
        float4 a0 = *(const float4*)(Aptr + k0);
        float4 a1 = *(const float4*)(Aptr + k0 + 4);
        float4 bv = *(const float4*)(Bptr + (long long)k0 * ldb);
        __syncthreads();
        As[acol+0][arow] = a0.x; As[acol+1][arow] = a0.y;
        As[acol+2][arow] = a0.z; As[acol+3][arow] = a0.w;
        As[acol+4][arow] = a1.x; As[acol+5][arow] = a1.y;
        As[acol+6][arow] = a1.z; As[acol+7][arow] = a1.w;
        *(float4*)&Bs[brow][bcol] = bv;
        __syncthreads();
        #pragma unroll
        for (int kk = 0; kk < 16; kk++) {
            float a[8], bb[4];
            #pragma unroll
            for (int i = 0; i < 8; i++) a[i]  = As[kk][ty*8 + i];
            #pragma unroll
            for (int j = 0; j < 4; j++) bb[j] = Bs[kk][tx*4 + j];
            #pragma unroll
            for (int i = 0; i < 8; i++)
                #pragma unroll
                for (int j = 0; j < 4; j++) acc[i][j] += a[i] * bb[j];
        }
    }

    #pragma unroll
    for (int i = 0; i < 8; i++) {
        long long m = m0 + ty*8 + i;
        #pragma unroll
        for (int j = 0; j < 4; j++) {
            long long n = n0 + tx*4 + j;
            Cm[m * ldc + n] = acc[i][j] * alpha;
        }
    }
}

// ---------------- per-row dual top-k select + combined softmax weights (in place) ----------------
// Exact kth-largest via 4x8-bit MSB-first radix select on sign-flipped float keys.
// Then W[i] = exp(a_i - m) * (0.6/Z1 * [a_i >= t1] + 0.4/Z2 * [a_i >= t2]).
__global__ void __launch_bounds__(256) select_kernel(const int* __restrict__ pk1,
                                                     const int* __restrict__ pk2)
{
    long long row = (long long)blockIdx.y * gridDim.x + blockIdx.x;   // z*1024 + q
    float* Srow = g_S + row * 1024;

    __shared__ float    sv[1024];
    __shared__ unsigned su[1024];
    __shared__ unsigned hist[256];
    __shared__ float    red[256];
    __shared__ unsigned s_prefix;
    __shared__ int      s_kk;

    int tid = threadIdx.x;

    #pragma unroll
    for (int i = 0; i < 4; i++) {
        int idx = tid + i * 256;
        float f = Srow[idx];
        sv[idx] = f;
        unsigned bts = __float_as_uint(f);
        su[idx] = (bts & 0x80000000u) ? ~bts : (bts | 0x80000000u);
    }
    __syncthreads();

    // row max
    float mx = sv[tid];
    #pragma unroll
    for (int i = 1; i < 4; i++) mx = fmaxf(mx, sv[tid + i*256]);
    red[tid] = mx;
    __syncthreads();
    for (int s = 128; s > 0; s >>= 1) {
        if (tid < s) red[tid] = fmaxf(red[tid], red[tid+s]);
        __syncthreads();
    }
    float m = red[0];

    int kks0 = *pk1, kks1 = *pk2;
    unsigned tkey[2];

    for (int t = 0; t < 2; t++) {
        if (tid == 0) { s_prefix = 0u; s_kk = (t == 0) ? kks0 : kks1; }
        __syncthreads();
        for (int byt = 3; byt >= 0; byt--) {
            int shift = byt * 8;
            unsigned himask = (byt == 3) ? 0u : (0xFFFFFFFFu << (shift + 8));
            unsigned pfx = s_prefix;
            hist[tid] = 0u;
            __syncthreads();
            #pragma unroll
            for (int i = 0; i < 4; i++) {
                unsigned u = su[tid + i*256];
                if (((u ^ pfx) & himask) == 0u)
                    atomicAdd(&hist[(u >> shift) & 255u], 1u);
            }
            __syncthreads();
            // suffix (descending) scan -> hist[i] = count of candidates with byte >= i
            for (int d = 1; d < 256; d <<= 1) {
                unsigned v = (tid + d < 256) ? hist[tid + d] : 0u;
                __syncthreads();
                hist[tid] += v;
                __syncthreads();
            }
            int kk = s_kk;
            unsigned here = hist[tid];
            unsigned nxt  = (tid < 255) ? hist[tid + 1] : 0u;
            __syncthreads();
            if (here >= (unsigned)kk && nxt < (unsigned)kk) {
                s_prefix = pfx | ((unsigned)tid << shift);
                s_kk     = kk - (int)nxt;
            }
            __syncthreads();
        }
        tkey[t] = s_prefix;
        __syncthreads();
    }

    // masked partition sums
    float z1 = 0.f, z2 = 0.f;
    #pragma unroll
    for (int i = 0; i < 4; i++) {
        int idx = tid + i * 256;
        unsigned u = su[idx];
        float e = __expf(sv[idx] - m);
        if (u >= tkey[0]) z1 += e;
        if (u >= tkey[1]) z2 += e;
    }
    red[tid] = z1; __syncthreads();
    for (int s = 128; s > 0; s >>= 1) { if (tid < s) red[tid] += red[tid+s]; __syncthreads(); }
    float Z1 = red[0];
    __syncthreads();
    red[tid] = z2; __syncthreads();
    for (int s = 128; s > 0; s >>= 1) { if (tid < s) red[tid] += red[tid+s]; __syncthreads(); }
    float Z2 = red[0];

    float c1 = 0.6f / Z1;
    float c2 = 0.4f / Z2;

    #pragma unroll
    for (int i = 0; i < 4; i++) {
        int idx = tid + i * 256;
        unsigned u = su[idx];
        float e = __expf(sv[idx] - m);
        float w = e * ((u >= tkey[0]) ? c1 : 0.f) + e * ((u >= tkey[1]) ? c2 : 0.f);
        Srow[idx] = w;
    }
}

// ---------------- launch ----------------
extern "C" void kernel_launch(void* const* d_in, const int* in_sizes, int n_in,
                              void* d_out, int out_size)
{
    const float* x   = (const float*)d_in[0];
    const float* y   = (const float*)d_in[1];
    const float* c1w = (const float*)d_in[2];
    const float* c1b = (const float*)d_in[3];
    const float* c2w = (const float*)d_in[4];
    const float* c2b = (const float*)d_in[5];
    const float* c3w = (const float*)d_in[6];
    const float* c3b = (const float*)d_in[7];
    const float* lnw = (const float*)d_in[8];
    const float* lnb = (const float*)d_in[9];
    const float* qw  = (const float*)d_in[10];
    const float* kvw = (const float*)d_in[11];
    const float* pw  = (const float*)d_in[12];
    const float* pb  = (const float*)d_in[13];
    const int*   pk1 = (const int*)d_in[14];
    const int*   pk2 = (const int*)d_in[15];
    float* out = (float*)d_out;

    float *ynorm, *q, *kv, *attn, *S;
    cudaGetSymbolAddress((void**)&ynorm, g_ynorm);
    cudaGetSymbolAddress((void**)&q,     g_q);
    cudaGetSymbolAddress((void**)&kv,    g_kv);
    cudaGetSymbolAddress((void**)&attn,  g_attn);
    cudaGetSymbolAddress((void**)&S,     g_S);

    // 1) multiscale depthwise conv + LN on y -> g_ynorm
    conv_ln_kernel<<<B_*NYk, 256>>>(y, c1w, c1b, c2w, c2b, c3w, c3b, lnw, lnb);

    // 2) q = x @ q_w^T   [4096,768]
    gemm_nt_128x128<0,0><<<dim3(768/128, 4096/128, 1), 256>>>(
        x, qw, q, nullptr, nullptr, 768, 768, 768, 768, 1.0f,
        1, 0, 0, 0, 0, 0, 0);

    // 3) kv = y_norm @ kv_w^T   [4096,1536]
    gemm_nt_128x128<0,0><<<dim3(1536/128, 4096/128, 1), 256>>>(
        ynorm, kvw, kv, nullptr, nullptr, 768, 768, 768, 1536, 1.0f,
        1, 0, 0, 0, 0, 0, 0);

    // 4) scores S[b,h] = (q_bh @ K_bh^T) * D^-0.5   48 x [1024,1024], K=64
    gemm_nt_128x128<0,0><<<dim3(8, 8, 48), 256>>>(
        q, kv, S, nullptr, nullptr, 64, 768, 1536, 1024, 0.125f,
        12, (long long)1024*768, 64,
            (long long)1024*1536, 64,
            (long long)12*1024*1024, (long long)1024*1024);

    // 5) per-row dual top-k -> combined softmax weights, in place in S
    select_kernel<<<dim3(1024, 48), 256>>>(pk1, pk2);

    // 6) attn = W @ V   48 x [1024,1024]@[1024,64] -> g_attn [B,NX,C] head-sliced
    gemm_nn_128x64<<<dim3(1, 8, 48), 256>>>(
        S, kv + 768, attn, 1024, 1024, 1536, 768, 1.0f,
        12, (long long)12*1024*1024, (long long)1024*1024,
            (long long)1024*1536, 64,
            (long long)1024*768, 64);

    // 7) out = attn @ proj_w^T + proj_b + x
    gemm_nt_128x128<1,1><<<dim3(768/128, 4096/128, 1), 256>>>(
        attn, pw, out, pb, x, 768, 768, 768, 768, 1.0f,
        1, 0, 0, 0, 0, 0, 0);
}

// round 3
// speedup vs baseline: 1.4184x; 1.4184x over previous
#include <cuda_runtime.h>
#include <cuda_bf16.h>
#include <cstdint>

#define B_  4
#define NXq 1024
#define NYk 1024
#define C_  768
#define H_  12
#define D_  64

// ======================= scratch (static device globals) =======================
__device__ float g_S[48u*1024u*1024u];                                   // fp32 scores
__device__ __align__(16) __nv_bfloat16 g_xh [B_*NXq*C_], g_xl [B_*NXq*C_];
__device__ __align__(16) __nv_bfloat16 g_ynh[B_*NYk*C_], g_ynl[B_*NYk*C_];
__device__ __align__(16) __nv_bfloat16 g_qh [B_*NXq*C_], g_ql [B_*NXq*C_];
__device__ __align__(16) __nv_bfloat16 g_kvh[B_*NYk*2*C_], g_kvl[B_*NYk*2*C_];
__device__ __align__(16) __nv_bfloat16 g_vth[48*64*1024], g_vtl[48*64*1024];
__device__ __align__(16) __nv_bfloat16 g_Wh [48u*1024u*1024u], g_Wl[48u*1024u*1024u];
__device__ __align__(16) __nv_bfloat16 g_ath[B_*NXq*C_], g_atl[B_*NXq*C_];
__device__ __align__(16) __nv_bfloat16 g_qwh [C_*C_],   g_qwl [C_*C_];
__device__ __align__(16) __nv_bfloat16 g_kvwh[2*C_*C_], g_kvwl[2*C_*C_];
__device__ __align__(16) __nv_bfloat16 g_pwh [C_*C_],   g_pwl [C_*C_];

__device__ __forceinline__ void split2(float v, __nv_bfloat16& h, __nv_bfloat16& l) {
    h = __float2bfloat16(v);
    l = __float2bfloat16(v - __bfloat162float(h));
}

// ======================= fused multiscale conv + LayerNorm -> bf16 split =======================
__global__ void __launch_bounds__(256) conv_ln_kernel(
    const float* __restrict__ y,
    const float* __restrict__ c1w, const float* __restrict__ c1b,
    const float* __restrict__ c2w, const float* __restrict__ c2b,
    const float* __restrict__ c3w, const float* __restrict__ c3b,
    const float* __restrict__ lnw, const float* __restrict__ lnb)
{
    int row = blockIdx.x;
    int b  = row >> 10;
    int ny = row & 1023;
    const float* yb = y + (size_t)b * NYk * C_;
    int tid = threadIdx.x;

    float vals[3];
    float lsum = 0.f, lsq = 0.f;
    #pragma unroll
    for (int i = 0; i < 3; i++) {
        int c = tid + i * 256;
        float w7[7];
        #pragma unroll
        for (int j = 0; j < 7; j++) w7[j] = c3w[c*7 + j];
        #pragma unroll
        for (int j = 0; j < 5; j++) w7[j+1] += c2w[c*5 + j];
        #pragma unroll
        for (int j = 0; j < 3; j++) w7[j+2] += c1w[c*3 + j];
        float acc = c1b[c] + c2b[c] + c3b[c];
        #pragma unroll
        for (int j = 0; j < 7; j++) {
            int nn = ny + j - 3;
            if (nn >= 0 && nn < NYk) acc += w7[j] * yb[(size_t)nn * C_ + c];
        }
        vals[i] = acc; lsum += acc; lsq += acc * acc;
    }

    __shared__ float s1[256], s2[256];
    s1[tid] = lsum; s2[tid] = lsq;
    __syncthreads();
    for (int s = 128; s > 0; s >>= 1) {
        if (tid < s) { s1[tid] += s1[tid+s]; s2[tid] += s2[tid+s]; }
        __syncthreads();
    }
    float mean = s1[0] * (1.0f / C_);
    float var  = s2[0] * (1.0f / C_) - mean * mean;
    float rstd = rsqrtf(var + 1e-5f);

    size_t base = (size_t)row * C_;
    #pragma unroll
    for (int i = 0; i < 3; i++) {
        int c = tid + i * 256;
        float v = (vals[i] - mean) * rstd * lnw[c] + lnb[c];
        __nv_bfloat16 h, l; split2(v, h, l);
        g_ynh[base + c] = h; g_ynl[base + c] = l;
    }
}

// ======================= fp32 -> bf16 split =======================
__global__ void __launch_bounds__(256) split_kernel(const float* __restrict__ s,
                                                    __nv_bfloat16* __restrict__ ho,
                                                    __nv_bfloat16* __restrict__ lo_,
                                                    int n4)
{
    int i = blockIdx.x * 256 + threadIdx.x;
    if (i >= n4) return;
    float4 v = ((const float4*)s)[i];
    __nv_bfloat16 h0,h1,h2,h3,l0,l1,l2,l3;
    split2(v.x,h0,l0); split2(v.y,h1,l1); split2(v.z,h2,l2); split2(v.w,h3,l3);
    __nv_bfloat162* H = (__nv_bfloat162*)ho;
    __nv_bfloat162* L = (__nv_bfloat162*)lo_;
    H[2*i]   = __halves2bfloat162(h0, h1);
    H[2*i+1] = __halves2bfloat162(h2, h3);
    L[2*i]   = __halves2bfloat162(l0, l1);
    L[2*i+1] = __halves2bfloat162(l2, l3);
}

// ======================= V transpose (bf16 split in -> transposed split out) =======================
__global__ void __launch_bounds__(256) vtrans_kernel()
{
    int z  = blockIdx.x;        // 0..47 = b*12+h
    int t0 = blockIdx.y * 32;   // token tile
    int b = z / 12, h = z - b*12;
    __shared__ __nv_bfloat16 sh[64][33], sl[64][33];
    int tid = threadIdx.x;
    #pragma unroll
    for (int i = 0; i < 8; i++) {
        int idx = tid + i*256;
        int tok = idx >> 6, d = idx & 63;
        size_t off = ((size_t)(b*1024 + t0 + tok)) * 1536 + 768 + h*64 + d;
        sh[d][tok] = g_kvh[off];
        sl[d][tok] = g_kvl[off];
    }
    __syncthreads();
    #pragma unroll
    for (int i = 0; i < 8; i++) {
        int o = tid + i*256;
        int d = o >> 5, c = o & 31;
        size_t off = (size_t)z * 64 * 1024 + (size_t)d * 1024 + t0 + c;
        g_vth[off] = sh[d][c];
        g_vtl[off] = sl[d][c];
    }
}

// ======================= HMMA GEMM: C = alpha * A @ B^T  (split-bf16, fp32 accum) =======================
// A: [M,K] K-major bf16 pair; B: [N,K] K-major bf16 pair.
// 3 extended-K segments: Ah*Bh + Ah*Bl + Al*Bh.
// Tile 128 x NT, 8 warps. OUTM: 0 = fp32*alpha; 1 = fp32*alpha+bias+res; 2 = bf16 split out.
template<int NT, int OUTM>
__global__ void __launch_bounds__(256) mma_gemm(
    const __nv_bfloat16* __restrict__ Ah, const __nv_bfloat16* __restrict__ Al,
    const __nv_bfloat16* __restrict__ Bh, const __nv_bfloat16* __restrict__ Bl,
    float* __restrict__ Co, __nv_bfloat16* __restrict__ Coh, __nv_bfloat16* __restrict__ Col,
    const float* __restrict__ bias, const float* __restrict__ res,
    int K, int lda, int ldb, int ldc, float alpha, int HH,
    long long aO, long long aI, long long bO, long long bI,
    long long cO, long long cI)
{
    constexpr int WM  = (NT == 128) ? 2 : 4;   // warps along M
    constexpr int WN  = 8 / WM;                // warps along N
    constexpr int WTM = 128 / WM;              // 64 or 32
    constexpr int WTN = NT / WN;               // 32
    constexpr int MT  = WTM / 16;              // 4 or 2
    constexpr int NTT = WTN / 8;               // 4
    constexpr int PITCH = 72;                  // bf16 elems per smem row (pad 8)

    __shared__ __nv_bfloat16 As[128 * PITCH];
    __shared__ __nv_bfloat16 Bs[NT  * PITCH];

    int tid = threadIdx.x, wid = tid >> 5, lane = tid & 31;
    int wm = wid % WM, wn = wid / WM;
    int gg = lane >> 2, qq = lane & 3;

    int z = blockIdx.z, zo = z / HH, zi = z - zo * HH;
    Ah += zo*aO + zi*aI; Al += zo*aO + zi*aI;
    Bh += zo*bO + zi*bI; Bl += zo*bO + zi*bI;
    long long coff = zo*cO + zi*cI;

    long long m0 = (long long)blockIdx.y * 128;
    long long n0 = (long long)blockIdx.x * NT;

    float acc[MT][NTT][4];
    #pragma unroll
    for (int i = 0; i < MT; i++)
        #pragma unroll
        for (int j = 0; j < NTT; j++)
            #pragma unroll
            for (int r = 0; r < 4; r++) acc[i][j][r] = 0.f;

    const __nv_bfloat16* As3[3] = {Ah, Ah, Al};
    const __nv_bfloat16* Bs3[3] = {Bh, Bl, Bh};

    int KT = K >> 6;
    for (int seg = 0; seg < 3; seg++) {
        const __nv_bfloat16* Ap = As3[seg];
        const __nv_bfloat16* Bp = Bs3[seg];
        for (int kc = 0; kc < KT; kc++) {
            int k0 = kc << 6;
            // global -> regs (overlaps previous compute)
            uint4 av[4];
            #pragma unroll
            for (int i = 0; i < 4; i++) {
                int ch = tid + (i << 8);
                int r = ch >> 3, c = (ch & 7) << 3;
                av[i] = *(const uint4*)(Ap + (m0 + r) * lda + k0 + c);
            }
            uint4 bv[NT / 32];
            #pragma unroll
            for (int i = 0; i < NT/32; i++) {
                int ch = tid + (i << 8);
                int r = ch >> 3, c = (ch & 7) << 3;
                bv[i] = *(const uint4*)(Bp + (n0 + r) * ldb + k0 + c);
            }
            __syncthreads();
            #pragma unroll
            for (int i = 0; i < 4; i++) {
                int ch = tid + (i << 8);
                int r = ch >> 3, c = (ch & 7) << 3;
                *(uint4*)&As[r * PITCH + c] = av[i];
            }
            #pragma unroll
            for (int i = 0; i < NT/32; i++) {
                int ch = tid + (i << 8);
                int r = ch >> 3, c = (ch & 7) << 3;
                *(uint4*)&Bs[r * PITCH + c] = bv[i];
            }
            __syncthreads();

            #pragma unroll
            for (int ks = 0; ks < 4; ks++) {
                int kb = ks << 4;
                uint32_t af[MT][4];
                #pragma unroll
                for (int mt = 0; mt < MT; mt++) {
                    const __nv_bfloat16* pa = &As[(wm*WTM + mt*16 + gg) * PITCH + kb + 2*qq];
                    af[mt][0] = *(const uint32_t*)pa;
                    af[mt][1] = *(const uint32_t*)(pa + 8*PITCH);
                    af[mt][2] = *(const uint32_t*)(pa + 8);
                    af[mt][3] = *(const uint32_t*)(pa + 8*PITCH + 8);
                }
                uint32_t bf[NTT][2];
                #pragma unroll
                for (int nt = 0; nt < NTT; nt++) {
                    const __nv_bfloat16* pb = &Bs[(wn*WTN + nt*8 + gg) * PITCH + kb + 2*qq];
                    bf[nt][0] = *(const uint32_t*)pb;
                    bf[nt][1] = *(const uint32_t*)(pb + 8);
                }
                #pragma unroll
                for (int mt = 0; mt < MT; mt++)
                    #pragma unroll
                    for (int nt = 0; nt < NTT; nt++) {
                        asm volatile(
                            "mma.sync.aligned.m16n8k16.row.col.f32.bf16.bf16.f32 "
                            "{%0,%1,%2,%3}, {%4,%5,%6,%7}, {%8,%9}, {%0,%1,%2,%3};"
                            : "+f"(acc[mt][nt][0]), "+f"(acc[mt][nt][1]),
                              "+f"(acc[mt][nt][2]), "+f"(acc[mt][nt][3])
                            : "r"(af[mt][0]), "r"(af[mt][1]), "r"(af[mt][2]), "r"(af[mt][3]),
                              "r"(bf[nt][0]), "r"(bf[nt][1]));
                    }
            }
        }
    }

    // epilogue: direct fragment stores
    #pragma unroll
    for (int mt = 0; mt < MT; mt++) {
        long long gm = m0 + wm*WTM + mt*16 + gg;
        #pragma unroll
        for (int nt = 0; nt < NTT; nt++) {
            long long gn = n0 + wn*WTN + nt*8 + 2*qq;
            float v0 = acc[mt][nt][0] * alpha;
            float v1 = acc[mt][nt][1] * alpha;
            float v2 = acc[mt][nt][2] * alpha;
            float v3 = acc[mt][nt][3] * alpha;
            long long gi0 = coff + gm * (long long)ldc + gn;
            long long gi1 = gi0 + 8LL * ldc;
            if (OUTM == 0) {
                *(float2*)&Co[gi0] = make_float2(v0, v1);
                *(float2*)&Co[gi1] = make_float2(v2, v3);
            } else if (OUTM == 1) {
                float b0 = bias[gn], b1 = bias[gn + 1];
                float2 r0 = *(const float2*)&res[gi0];
                float2 r1 = *(const float2*)&res[gi1];
                *(float2*)&Co[gi0] = make_float2(v0 + b0 + r0.x, v1 + b1 + r0.y);
                *(float2*)&Co[gi1] = make_float2(v2 + b0 + r1.x, v3 + b1 + r1.y);
            } else {
                __nv_bfloat16 h0,l0,h1,l1,h2,l2,h3,l3;
                split2(v0,h0,l0); split2(v1,h1,l1); split2(v2,h2,l2); split2(v3,h3,l3);
                *(__nv_bfloat162*)&Coh[gi0] = __halves2bfloat162(h0, h1);
                *(__nv_bfloat162*)&Coh[gi1] = __halves2bfloat162(h2, h3);
                *(__nv_bfloat162*)&Col[gi0] = __halves2bfloat162(l0, l1);
                *(__nv_bfloat162*)&Col[gi1] = __halves2bfloat162(l2, l3);
            }
        }
    }
}

// ======================= dual top-k select -> combined softmax weights (bf16 split) =======================
__global__ void __launch_bounds__(256) select_kernel(const int* __restrict__ pk1,
                                                     const int* __restrict__ pk2)
{
    long long row = (long long)blockIdx.y * gridDim.x + blockIdx.x;
    const float* Srow = g_S + row * 1024;

    __shared__ float    sv[1024];
    __shared__ unsigned su[1024];
    __shared__ unsigned hist[256];
    __shared__ float    red[256];
    __shared__ unsigned s_prefix;
    __shared__ int      s_kk;

    int tid = threadIdx.x;

    #pragma unroll
    for (int i = 0; i < 4; i++) {
        int idx = tid + i * 256;
        float f = Srow[idx];
        sv[idx] = f;
        unsigned bts = __float_as_uint(f);
        su[idx] = (bts & 0x80000000u) ? ~bts : (bts | 0x80000000u);
    }
    __syncthreads();

    float mx = sv[tid];
    #pragma unroll
    for (int i = 1; i < 4; i++) mx = fmaxf(mx, sv[tid + i*256]);
    red[tid] = mx;
    __syncthreads();
    for (int s = 128; s > 0; s >>= 1) {
        if (tid < s) red[tid] = fmaxf(red[tid], red[tid+s]);
        __syncthreads();
    }
    float m = red[0];

    int kks0 = *pk1, kks1 = *pk2;
    unsigned tkey[2];

    for (int t = 0; t < 2; t++) {
        if (tid == 0) { s_prefix = 0u; s_kk = (t == 0) ? kks0 : kks1; }
        __syncthreads();
        for (int byt = 3; byt >= 0; byt--) {
            int shift = byt * 8;
            unsigned himask = (byt == 3) ? 0u : (0xFFFFFFFFu << (shift + 8));
            unsigned pfx = s_prefix;
            hist[tid] = 0u;
            __syncthreads();
            #pragma unroll
            for (int i = 0; i < 4; i++) {
                unsigned u = su[tid + i*256];
                if (((u ^ pfx) & himask) == 0u)
                    atomicAdd(&hist[(u >> shift) & 255u], 1u);
            }
            __syncthreads();
            for (int d = 1; d < 256; d <<= 1) {
                unsigned v = (tid + d < 256) ? hist[tid + d] : 0u;
                __syncthreads();
                hist[tid] += v;
                __syncthreads();
            }
            int kk = s_kk;
            unsigned here = hist[tid];
            unsigned nxt  = (tid < 255) ? hist[tid + 1] : 0u;
            __syncthreads();
            if (here >= (unsigned)kk && nxt < (unsigned)kk) {
                s_prefix = pfx | ((unsigned)tid << shift);
                s_kk     = kk - (int)nxt;
            }
            __syncthreads();
        }
        tkey[t] = s_prefix;
        __syncthreads();
    }

    float z1 = 0.f, z2 = 0.f;
    #pragma unroll
    for (int i = 0; i < 4; i++) {
        int idx = tid + i * 256;
        unsigned u = su[idx];
        float e = __expf(sv[idx] - m);
        if (u >= tkey[0]) z1 += e;
        if (u >= tkey[1]) z2 += e;
    }
    red[tid] = z1; __syncthreads();
    for (int s = 128; s > 0; s >>= 1) { if (tid < s) red[tid] += red[tid+s]; __syncthreads(); }
    float Z1 = red[0];
    __syncthreads();
    red[tid] = z2; __syncthreads();
    for (int s = 128; s > 0; s >>= 1) { if (tid < s) red[tid] += red[tid+s]; __syncthreads(); }
    float Z2 = red[0];

    float c1 = 0.6f / Z1;
    float c2 = 0.4f / Z2;

    long long obase = row * 1024;
    #pragma unroll
    for (int i = 0; i < 4; i++) {
        int idx = tid + i * 256;
        unsigned u = su[idx];
        float e = __expf(sv[idx] - m);
        float w = e * ((u >= tkey[0]) ? c1 : 0.f) + e * ((u >= tkey[1]) ? c2 : 0.f);
        __nv_bfloat16 h, l; split2(w, h, l);
        g_Wh[obase + idx] = h;
        g_Wl[obase + idx] = l;
    }
}

// ======================= launch =======================
extern "C" void kernel_launch(void* const* d_in, const int* in_sizes, int n_in,
                              void* d_out, int out_size)
{
    const float* x   = (const float*)d_in[0];
    const float* y   = (const float*)d_in[1];
    const float* c1w = (const float*)d_in[2];
    const float* c1b = (const float*)d_in[3];
    const float* c2w = (const float*)d_in[4];
    const float* c2b = (const float*)d_in[5];
    const float* c3w = (const float*)d_in[6];
    const float* c3b = (const float*)d_in[7];
    const float* lnw = (const float*)d_in[8];
    const float* lnb = (const float*)d_in[9];
    const float* qw  = (const float*)d_in[10];
    const float* kvw = (const float*)d_in[11];
    const float* pw  = (const float*)d_in[12];
    const float* pb  = (const float*)d_in[13];
    const int*   pk1 = (const int*)d_in[14];
    const int*   pk2 = (const int*)d_in[15];
    float* out = (float*)d_out;

    #define SYM(p, g) void* p; cudaGetSymbolAddress(&p, g)
    SYM(S, g_S);
    SYM(xh, g_xh);   SYM(xl, g_xl);
    SYM(qh, g_qh);   SYM(ql, g_ql);
    SYM(ynh, g_ynh); SYM(ynl, g_ynl);
    SYM(kvh, g_kvh); SYM(kvl, g_kvl);
    SYM(vth, g_vth); SYM(vtl, g_vtl);
    SYM(Wh, g_Wh);   SYM(Wl, g_Wl);
    SYM(ath, g_ath); SYM(atl, g_atl);
    SYM(qwh, g_qwh); SYM(qwl, g_qwl);
    SYM(kvwh, g_kvwh); SYM(kvwl, g_kvwl);
    SYM(pwh, g_pwh); SYM(pwl, g_pwl);
    #undef SYM

    // 1) conv + LN -> ynorm split
    conv_ln_kernel<<<B_*NYk, 256>>>(y, c1w, c1b, c2w, c2b, c3w, c3b, lnw, lnb);

    // 2) splits of x and weights
    split_kernel<<<3072, 256>>>(x,  (__nv_bfloat16*)xh,  (__nv_bfloat16*)xl,  786432);
    split_kernel<<<576,  256>>>(qw, (__nv_bfloat16*)qwh, (__nv_bfloat16*)qwl, 147456);
    split_kernel<<<1152, 256>>>(kvw,(__nv_bfloat16*)kvwh,(__nv_bfloat16*)kvwl,294912);
    split_kernel<<<576,  256>>>(pw, (__nv_bfloat16*)pwh, (__nv_bfloat16*)pwl, 147456);

    // 3) q = x @ q_w^T  -> split
    mma_gemm<128,2><<<dim3(6,32,1), 256>>>(
        (const __nv_bfloat16*)xh, (const __nv_bfloat16*)xl,
        (const __nv_bfloat16*)qwh, (const __nv_bfloat16*)qwl,
        nullptr, (__nv_bfloat16*)qh, (__nv_bfloat16*)ql, nullptr, nullptr,
        768, 768, 768, 768, 1.0f, 1, 0,0,0,0,0,0);

    // 4) kv = y_norm @ kv_w^T -> split
    mma_gemm<128,2><<<dim3(12,32,1), 256>>>(
        (const __nv_bfloat16*)ynh, (const __nv_bfloat16*)ynl,
        (const __nv_bfloat16*)kvwh, (const __nv_bfloat16*)kvwl,
        nullptr, (__nv_bfloat16*)kvh, (__nv_bfloat16*)kvl, nullptr, nullptr,
        768, 768, 768, 1536, 1.0f, 1, 0,0,0,0,0,0);

    // 5) V^T split
    vtrans_kernel<<<dim3(48,32), 256>>>();

    // 6) scores S = (q @ K^T) * D^-0.5  (48 heads)
    mma_gemm<128,0><<<dim3(8,8,48), 256>>>(
        (const __nv_bfloat16*)qh, (const __nv_bfloat16*)ql,
        (const __nv_bfloat16*)kvh, (const __nv_bfloat16*)kvl,
        (float*)S, nullptr, nullptr, nullptr, nullptr,
        64, 768, 1536, 1024, 0.125f, 12,
        (long long)1024*768, 64,
        (long long)1024*1536, 64,
        (long long)12*1024*1024, (long long)1024*1024);

    // 7) dual top-k -> combined weights W (bf16 split)
    select_kernel<<<dim3(1024, 48), 256>>>(pk1, pk2);

    // 8) attn = W @ V^T  -> split
    mma_gemm<64,2><<<dim3(1,8,48), 256>>>(
        (const __nv_bfloat16*)Wh, (const __nv_bfloat16*)Wl,
        (const __nv_bfloat16*)vth, (const __nv_bfloat16*)vtl,
        nullptr, (__nv_bfloat16*)ath, (__nv_bfloat16*)atl, nullptr, nullptr,
        1024, 1024, 1024, 768, 1.0f, 12,
        (long long)12*1024*1024, (long long)1024*1024,
        (long long)12*64*1024,   (long long)64*1024,
        (long long)1024*768, 64);

    // 9) out = attn @ proj_w^T + proj_b + x
    mma_gemm<128,1><<<dim3(6,32,1), 256>>>(
        (const __nv_bfloat16*)ath, (const __nv_bfloat16*)atl,
        (const __nv_bfloat16*)pwh, (const __nv_bfloat16*)pwl,
        out, nullptr, nullptr, pb, x,
        768, 768, 768, 768, 1.0f, 1, 0,0,0,0,0,0);
}

// round 4
// speedup vs baseline: 2.4513x; 1.7282x over previous
#include <cuda_runtime.h>
#include <cuda_bf16.h>
#include <cstdint>

#define B_  4
#define NXq 1024
#define NYk 1024
#define C_  768
#define H_  12
#define D_  64

// ======================= scratch (static device globals) =======================
__device__ float g_S[48u*1024u*1024u];                                   // fp32 scores
__device__ __align__(16) __nv_bfloat16 g_xh [B_*NXq*C_], g_xl [B_*NXq*C_];
__device__ __align__(16) __nv_bfloat16 g_ynh[B_*NYk*C_], g_ynl[B_*NYk*C_];
__device__ __align__(16) __nv_bfloat16 g_qh [B_*NXq*C_], g_ql [B_*NXq*C_];
__device__ __align__(16) __nv_bfloat16 g_kvh[B_*NYk*2*C_], g_kvl[B_*NYk*2*C_];
__device__ __align__(16) __nv_bfloat16 g_vth[48*64*1024], g_vtl[48*64*1024];
__device__ __align__(16) __nv_bfloat16 g_W  [48u*1024u*1024u];           // single bf16 weights
__device__ __align__(16) __nv_bfloat16 g_ath[B_*NXq*C_], g_atl[B_*NXq*C_];
__device__ __align__(16) __nv_bfloat16 g_qwh [C_*C_],   g_qwl [C_*C_];
__device__ __align__(16) __nv_bfloat16 g_kvwh[2*C_*C_], g_kvwl[2*C_*C_];
__device__ __align__(16) __nv_bfloat16 g_pwh [C_*C_],   g_pwl [C_*C_];

__device__ __forceinline__ void split2(float v, __nv_bfloat16& h, __nv_bfloat16& l) {
    h = __float2bfloat16(v);
    l = __float2bfloat16(v - __bfloat162float(h));
}
__device__ __forceinline__ uint32_t smem_u32(const void* p) {
    uint32_t a;
    asm("{ .reg .u64 t; cvta.to.shared.u64 t, %1; cvt.u32.u64 %0, t; }" : "=r"(a) : "l"(p));
    return a;
}
__device__ __forceinline__ void cp16(uint32_t dst, const void* src) {
    asm volatile("cp.async.cg.shared.global [%0], [%1], 16;" :: "r"(dst), "l"(src));
}

// ======================= fused multiscale conv + LayerNorm -> bf16 split =======================
__global__ void __launch_bounds__(256) conv_ln_kernel(
    const float* __restrict__ y,
    const float* __restrict__ c1w, const float* __restrict__ c1b,
    const float* __restrict__ c2w, const float* __restrict__ c2b,
    const float* __restrict__ c3w, const float* __restrict__ c3b,
    const float* __restrict__ lnw, const float* __restrict__ lnb)
{
    int row = blockIdx.x;
    int b  = row >> 10;
    int ny = row & 1023;
    const float* yb = y + (size_t)b * NYk * C_;
    int tid = threadIdx.x;

    float vals[3];
    float lsum = 0.f, lsq = 0.f;
    #pragma unroll
    for (int i = 0; i < 3; i++) {
        int c = tid + i * 256;
        float w7[7];
        #pragma unroll
        for (int j = 0; j < 7; j++) w7[j] = c3w[c*7 + j];
        #pragma unroll
        for (int j = 0; j < 5; j++) w7[j+1] += c2w[c*5 + j];
        #pragma unroll
        for (int j = 0; j < 3; j++) w7[j+2] += c1w[c*3 + j];
        float acc = c1b[c] + c2b[c] + c3b[c];
        #pragma unroll
        for (int j = 0; j < 7; j++) {
            int nn = ny + j - 3;
            if (nn >= 0 && nn < NYk) acc += w7[j] * yb[(size_t)nn * C_ + c];
        }
        vals[i] = acc; lsum += acc; lsq += acc * acc;
    }

    __shared__ float s1[256], s2[256];
    s1[tid] = lsum; s2[tid] = lsq;
    __syncthreads();
    for (int s = 128; s > 0; s >>= 1) {
        if (tid < s) { s1[tid] += s1[tid+s]; s2[tid] += s2[tid+s]; }
        __syncthreads();
    }
    float mean = s1[0] * (1.0f / C_);
    float var  = s2[0] * (1.0f / C_) - mean * mean;
    float rstd = rsqrtf(var + 1e-5f);

    size_t base = (size_t)row * C_;
    #pragma unroll
    for (int i = 0; i < 3; i++) {
        int c = tid + i * 256;
        float v = (vals[i] - mean) * rstd * lnw[c] + lnb[c];
        __nv_bfloat16 h, l; split2(v, h, l);
        g_ynh[base + c] = h; g_ynl[base + c] = l;
    }
}

// ======================= fp32 -> bf16 split =======================
__global__ void __launch_bounds__(256) split_kernel(const float* __restrict__ s,
                                                    __nv_bfloat16* __restrict__ ho,
                                                    __nv_bfloat16* __restrict__ lo_,
                                                    int n4)
{
    int i = blockIdx.x * 256 + threadIdx.x;
    if (i >= n4) return;
    float4 v = ((const float4*)s)[i];
    __nv_bfloat16 h0,h1,h2,h3,l0,l1,l2,l3;
    split2(v.x,h0,l0); split2(v.y,h1,l1); split2(v.z,h2,l2); split2(v.w,h3,l3);
    __nv_bfloat162* H = (__nv_bfloat162*)ho;
    __nv_bfloat162* L = (__nv_bfloat162*)lo_;
    H[2*i]   = __halves2bfloat162(h0, h1);
    H[2*i+1] = __halves2bfloat162(h2, h3);
    L[2*i]   = __halves2bfloat162(l0, l1);
    L[2*i+1] = __halves2bfloat162(l2, l3);
}

// ======================= V transpose (bf16 split in -> transposed split out) =======================
__global__ void __launch_bounds__(256) vtrans_kernel()
{
    int z  = blockIdx.x;        // 0..47 = b*12+h
    int t0 = blockIdx.y * 32;   // token tile
    int b = z / 12, h = z - b*12;
    __shared__ __nv_bfloat16 sh[64][33], sl[64][33];
    int tid = threadIdx.x;
    #pragma unroll
    for (int i = 0; i < 8; i++) {
        int idx = tid + i*256;
        int tok = idx >> 6, d = idx & 63;
        size_t off = ((size_t)(b*1024 + t0 + tok)) * 1536 + 768 + h*64 + d;
        sh[d][tok] = g_kvh[off];
        sl[d][tok] = g_kvl[off];
    }
    __syncthreads();
    #pragma unroll
    for (int i = 0; i < 8; i++) {
        int o = tid + i*256;
        int d = o >> 5, c = o & 31;
        size_t off = (size_t)z * 64 * 1024 + (size_t)d * 1024 + t0 + c;
        g_vth[off] = sh[d][c];
        g_vtl[off] = sl[d][c];
    }
}

// ======================= HMMA GEMM: C = alpha * A @ B^T  (split-bf16, fp32 accum) =======================
// cp.async double-buffered, ldmatrix fragments. Tile 128 x NT, 8 warps.
// SEGS=3: AhBh + AhBl + AlBh.  SEGS=2: A(Bh) + A(Bl) with single A.
// OUTM: 0 = fp32*alpha; 1 = fp32*alpha+bias+res; 2 = bf16 split out.
template<int NT, int OUTM, int SEGS>
__global__ void __launch_bounds__(256) mma_gemm(
    const __nv_bfloat16* __restrict__ Ah, const __nv_bfloat16* __restrict__ Al,
    const __nv_bfloat16* __restrict__ Bh, const __nv_bfloat16* __restrict__ Bl,
    float* __restrict__ Co, __nv_bfloat16* __restrict__ Coh, __nv_bfloat16* __restrict__ Col,
    const float* __restrict__ bias, const float* __restrict__ res,
    int K, int lda, int ldb, int ldc, float alpha, int HH,
    long long aO, long long aI, long long bO, long long bI,
    long long cO, long long cI)
{
    constexpr int WM  = (NT == 128) ? 2 : 4;
    constexpr int WN  = 8 / WM;
    constexpr int WTM = 128 / WM;
    constexpr int WTN = NT / WN;
    constexpr int MT  = WTM / 16;
    constexpr int NTT = WTN / 8;
    constexpr int PITCH = 72;                    // bf16 elems per smem row
    constexpr int ABYTES = 128 * PITCH * 2;
    constexpr int BBYTES = NT  * PITCH * 2;
    constexpr int STAGE  = ABYTES + BBYTES;

    extern __shared__ __align__(16) char dsm[];
    uint32_t smbase = smem_u32(dsm);

    int tid = threadIdx.x, wid = tid >> 5, lane = tid & 31;
    int wm = wid % WM, wn = wid / WM;

    int z = blockIdx.z, zo = z / HH, zi = z - zo * HH;
    Ah += zo*aO + zi*aI; Al += zo*aO + zi*aI;
    Bh += zo*bO + zi*bI; Bl += zo*bO + zi*bI;
    long long coff = zo*cO + zi*cI;

    long long m0 = (long long)blockIdx.y * 128;
    long long n0 = (long long)blockIdx.x * NT;

    float acc[MT][NTT][4];
    #pragma unroll
    for (int i = 0; i < MT; i++)
        #pragma unroll
        for (int j = 0; j < NTT; j++)
            #pragma unroll
            for (int r = 0; r < 4; r++) acc[i][j][r] = 0.f;

    const __nv_bfloat16* As3[3];
    const __nv_bfloat16* Bs3[3];
    if (SEGS == 3) { As3[0]=Ah; As3[1]=Ah; As3[2]=Al; Bs3[0]=Bh; Bs3[1]=Bl; Bs3[2]=Bh; }
    else           { As3[0]=Ah; As3[1]=Ah; As3[2]=Ah; Bs3[0]=Bh; Bs3[1]=Bl; Bs3[2]=Bh; }

    int KT = K >> 6;
    int nIter = SEGS * KT;

    // per-lane ldmatrix base offsets (bytes) within a stage
    uint32_t a_off = ((uint32_t)(wm*WTM + (lane & 15)) * PITCH + ((lane >> 4) << 3)) * 2;
    uint32_t b_off = ABYTES + ((uint32_t)(wn*WTN + (lane & 7)) * PITCH + (((lane >> 3) & 1) << 3)) * 2;

    auto issue = [&](int t) {
        int seg = t / KT, kc = t - seg * KT, k0 = kc << 6, s = t & 1;
        const __nv_bfloat16* Ap = As3[seg];
        const __nv_bfloat16* Bp = Bs3[seg];
        uint32_t sa = smbase + s * STAGE;
        uint32_t sb = sa + ABYTES;
        #pragma unroll
        for (int i = 0; i < 4; i++) {
            int ch = tid + (i << 8);
            int r = ch >> 3, c = (ch & 7) << 3;
            cp16(sa + (uint32_t)(r*PITCH + c)*2, Ap + (m0 + r)*lda + k0 + c);
        }
        #pragma unroll
        for (int i = 0; i < NT/32; i++) {
            int ch = tid + (i << 8);
            int r = ch >> 3, c = (ch & 7) << 3;
            cp16(sb + (uint32_t)(r*PITCH + c)*2, Bp + (n0 + r)*ldb + k0 + c);
        }
        asm volatile("cp.async.commit_group;");
    };

    issue(0);
    for (int t = 0; t < nIter; t++) {
        if (t + 1 < nIter) {
            issue(t + 1);
            asm volatile("cp.async.wait_group 1;");
        } else {
            asm volatile("cp.async.wait_group 0;");
        }
        __syncthreads();
        uint32_t stg = smbase + (uint32_t)(t & 1) * STAGE;
        uint32_t abase = stg + a_off;
        uint32_t bbase = stg + b_off;

        #pragma unroll
        for (int ks = 0; ks < 4; ks++) {
            uint32_t kb = (uint32_t)ks << 5;    // ks*16 elems * 2B
            uint32_t af[MT][4];
            #pragma unroll
            for (int mt = 0; mt < MT; mt++) {
                asm volatile("ldmatrix.sync.aligned.m8n8.x4.shared.b16 {%0,%1,%2,%3}, [%4];"
                    : "=r"(af[mt][0]), "=r"(af[mt][1]), "=r"(af[mt][2]), "=r"(af[mt][3])
                    : "r"(abase + (uint32_t)(mt*16*PITCH*2) + kb));
            }
            uint32_t bf[NTT][2];
            #pragma unroll
            for (int nt = 0; nt < NTT; nt++) {
                asm volatile("ldmatrix.sync.aligned.m8n8.x2.shared.b16 {%0,%1}, [%2];"
                    : "=r"(bf[nt][0]), "=r"(bf[nt][1])
                    : "r"(bbase + (uint32_t)(nt*8*PITCH*2) + kb));
            }
            #pragma unroll
            for (int mt = 0; mt < MT; mt++)
                #pragma unroll
                for (int nt = 0; nt < NTT; nt++) {
                    asm volatile(
                        "mma.sync.aligned.m16n8k16.row.col.f32.bf16.bf16.f32 "
                        "{%0,%1,%2,%3}, {%4,%5,%6,%7}, {%8,%9}, {%0,%1,%2,%3};"
                        : "+f"(acc[mt][nt][0]), "+f"(acc[mt][nt][1]),
                          "+f"(acc[mt][nt][2]), "+f"(acc[mt][nt][3])
                        : "r"(af[mt][0]), "r"(af[mt][1]), "r"(af[mt][2]), "r"(af[mt][3]),
                          "r"(bf[nt][0]), "r"(bf[nt][1]));
                }
        }
        __syncthreads();
    }

    int gg = lane >> 2, qq = lane & 3;
    #pragma unroll
    for (int mt = 0; mt < MT; mt++) {
        long long gm = m0 + wm*WTM + mt*16 + gg;
        #pragma unroll
        for (int nt = 0; nt < NTT; nt++) {
            long long gn = n0 + wn*WTN + nt*8 + 2*qq;
            float v0 = acc[mt][nt][0] * alpha;
            float v1 = acc[mt][nt][1] * alpha;
            float v2 = acc[mt][nt][2] * alpha;
            float v3 = acc[mt][nt][3] * alpha;
            long long gi0 = coff + gm * (long long)ldc + gn;
            long long gi1 = gi0 + 8LL * ldc;
            if (OUTM == 0) {
                *(float2*)&Co[gi0] = make_float2(v0, v1);
                *(float2*)&Co[gi1] = make_float2(v2, v3);
            } else if (OUTM == 1) {
                float b0 = bias[gn], b1 = bias[gn + 1];
                float2 r0 = *(const float2*)&res[gi0];
                float2 r1 = *(const float2*)&res[gi1];
                *(float2*)&Co[gi0] = make_float2(v0 + b0 + r0.x, v1 + b1 + r0.y);
                *(float2*)&Co[gi1] = make_float2(v2 + b0 + r1.x, v3 + b1 + r1.y);
            } else {
                __nv_bfloat16 h0,l0,h1,l1,h2,l2,h3,l3;
                split2(v0,h0,l0); split2(v1,h1,l1); split2(v2,h2,l2); split2(v3,h3,l3);
                *(__nv_bfloat162*)&Coh[gi0] = __halves2bfloat162(h0, h1);
                *(__nv_bfloat162*)&Coh[gi1] = __halves2bfloat162(h2, h3);
                *(__nv_bfloat162*)&Col[gi0] = __halves2bfloat162(l0, l1);
                *(__nv_bfloat162*)&Col[gi1] = __halves2bfloat162(l2, l3);
            }
        }
    }
}

// ======================= dual top-k select -> combined softmax weights (bf16) =======================
// Warp-shfl radix select, keys in registers, shared top-level histogram.
__global__ void __launch_bounds__(256) select_kernel(const int* __restrict__ pk1,
                                                     const int* __restrict__ pk2)
{
    long long row = (long long)blockIdx.y * gridDim.x + blockIdx.x;
    const float* Srow = g_S + row * 1024;

    __shared__ unsigned hist[512];
    __shared__ unsigned warr[16];
    __shared__ float    fred[16];
    __shared__ unsigned s_p[2];
    __shared__ int      s_k[2];
    __shared__ float    s_m, s_z1, s_z2;

    int tid = threadIdx.x, lane = tid & 31, wid = tid >> 5;

    float v[4]; unsigned u[4];
    float mx = -3.4e38f;
    #pragma unroll
    for (int i = 0; i < 4; i++) {
        float f = Srow[tid + i*256];
        v[i] = f;
        unsigned b = __float_as_uint(f);
        u[i] = (b & 0x80000000u) ? ~b : (b | 0x80000000u);
        mx = fmaxf(mx, f);
    }
    #pragma unroll
    for (int d = 16; d > 0; d >>= 1) mx = fmaxf(mx, __shfl_xor_sync(0xFFFFFFFFu, mx, d));
    if (lane == 0) fred[wid] = mx;

    int k1 = *pk1, k2 = *pk2;

    // ---- level 3 (shared histogram) ----
    hist[tid] = 0u; hist[tid + 256] = 0u;
    __syncthreads();
    if (tid == 0) {
        float m = fred[0];
        #pragma unroll
        for (int w = 1; w < 8; w++) m = fmaxf(m, fred[w]);
        s_m = m;
    }
    #pragma unroll
    for (int i = 0; i < 4; i++) atomicAdd(&hist[u[i] >> 24], 1u);
    __syncthreads();
    {
        unsigned cnt = hist[tid];
        unsigned s = cnt;
        #pragma unroll
        for (int d = 1; d < 32; d <<= 1) {
            unsigned t = __shfl_down_sync(0xFFFFFFFFu, s, d);
            if (lane + d < 32) s += t;
        }
        if (lane == 0) warr[wid] = s;
        __syncthreads();
        unsigned cross = 0;
        #pragma unroll
        for (int w = 0; w < 8; w++) if (w > wid) cross += warr[w];
        unsigned here = s + cross, nxt = here - cnt;
        if (here >= (unsigned)k1 && nxt < (unsigned)k1) { s_p[0] = (unsigned)tid << 24; s_k[0] = k1 - (int)nxt; }
        if (here >= (unsigned)k2 && nxt < (unsigned)k2) { s_p[1] = (unsigned)tid << 24; s_k[1] = k2 - (int)nxt; }
    }
    __syncthreads();

    // ---- levels 2..0 ----
    #pragma unroll
    for (int lev = 2; lev >= 0; lev--) {
        int sh = lev * 8;
        unsigned p1 = s_p[0], p2 = s_p[1];
        int kk1 = s_k[0], kk2 = s_k[1];
        bool same = (p1 == p2);
        unsigned himask = 0xFFFFFFFFu << (sh + 8);
        __syncthreads();
        hist[tid] = 0u; hist[tid + 256] = 0u;
        __syncthreads();
        #pragma unroll
        for (int i = 0; i < 4; i++) {
            unsigned uu = u[i];
            if (((uu ^ p1) & himask) == 0u) atomicAdd(&hist[(uu >> sh) & 255u], 1u);
            if (!same && ((uu ^ p2) & himask) == 0u) atomicAdd(&hist[256 + ((uu >> sh) & 255u)], 1u);
        }
        __syncthreads();
        {
            unsigned cnt1 = hist[tid];
            unsigned cnt2 = same ? cnt1 : hist[tid + 256];
            unsigned s1 = cnt1, s2 = cnt2;
            #pragma unroll
            for (int d = 1; d < 32; d <<= 1) {
                unsigned t1 = __shfl_down_sync(0xFFFFFFFFu, s1, d);
                unsigned t2 = __shfl_down_sync(0xFFFFFFFFu, s2, d);
                if (lane + d < 32) { s1 += t1; s2 += t2; }
            }
            if (lane == 0) { warr[wid] = s1; warr[8 + wid] = s2; }
            __syncthreads();
            unsigned cr1 = 0, cr2 = 0;
            #pragma unroll
            for (int w = 0; w < 8; w++) if (w > wid) { cr1 += warr[w]; cr2 += warr[8 + w]; }
            unsigned here1 = s1 + cr1, nxt1 = here1 - cnt1;
            unsigned here2 = s2 + cr2, nxt2 = here2 - cnt2;
            if (here1 >= (unsigned)kk1 && nxt1 < (unsigned)kk1) { s_p[0] = p1 | ((unsigned)tid << sh); s_k[0] = kk1 - (int)nxt1; }
            if (here2 >= (unsigned)kk2 && nxt2 < (unsigned)kk2) { s_p[1] = p2 | ((unsigned)tid << sh); s_k[1] = kk2 - (int)nxt2; }
        }
        __syncthreads();
    }

    unsigned t1 = s_p[0], t2 = s_p[1];
    float m = s_m;
    float e[4];
    float z1 = 0.f, z2 = 0.f;
    #pragma unroll
    for (int i = 0; i < 4; i++) {
        e[i] = __expf(v[i] - m);
        if (u[i] >= t1) z1 += e[i];
        if (u[i] >= t2) z2 += e[i];
    }
    #pragma unroll
    for (int d = 16; d > 0; d >>= 1) {
        z1 += __shfl_xor_sync(0xFFFFFFFFu, z1, d);
        z2 += __shfl_xor_sync(0xFFFFFFFFu, z2, d);
    }
    if (lane == 0) { fred[wid] = z1; fred[8 + wid] = z2; }
    __syncthreads();
    if (tid == 0) {
        float a = 0.f, b = 0.f;
        #pragma unroll
        for (int w = 0; w < 8; w++) { a += fred[w]; b += fred[8 + w]; }
        s_z1 = a; s_z2 = b;
    }
    __syncthreads();
    float c1 = 0.6f / s_z1;
    float c2 = 0.4f / s_z2;

    long long obase = row * 1024;
    #pragma unroll
    for (int i = 0; i < 4; i++) {
        float w = e[i] * ((u[i] >= t1) ? c1 : 0.f) + e[i] * ((u[i] >= t2) ? c2 : 0.f);
        g_W[obase + tid + i*256] = __float2bfloat16(w);
    }
}

// ======================= launch =======================
extern "C" void kernel_launch(void* const* d_in, const int* in_sizes, int n_in,
                              void* d_out, int out_size)
{
    const float* x   = (const float*)d_in[0];
    const float* y   = (const float*)d_in[1];
    const float* c1w = (const float*)d_in[2];
    const float* c1b = (const float*)d_in[3];
    const float* c2w = (const float*)d_in[4];
    const float* c2b = (const float*)d_in[5];
    const float* c3w = (const float*)d_in[6];
    const float* c3b = (const float*)d_in[7];
    const float* lnw = (const float*)d_in[8];
    const float* lnb = (const float*)d_in[9];
    const float* qw  = (const float*)d_in[10];
    const float* kvw = (const float*)d_in[11];
    const float* pw  = (const float*)d_in[12];
    const float* pb  = (const float*)d_in[13];
    const int*   pk1 = (const int*)d_in[14];
    const int*   pk2 = (const int*)d_in[15];
    float* out = (float*)d_out;

    #define SYM(p, g) void* p; cudaGetSymbolAddress(&p, g)
    SYM(S, g_S);
    SYM(xh, g_xh);   SYM(xl, g_xl);
    SYM(qh, g_qh);   SYM(ql, g_ql);
    SYM(ynh, g_ynh); SYM(ynl, g_ynl);
    SYM(kvh, g_kvh); SYM(kvl, g_kvl);
    SYM(vth, g_vth); SYM(vtl, g_vtl);
    SYM(W, g_W);
    SYM(ath, g_ath); SYM(atl, g_atl);
    SYM(qwh, g_qwh); SYM(qwl, g_qwl);
    SYM(kvwh, g_kvwh); SYM(kvwl, g_kvwl);
    SYM(pwh, g_pwh); SYM(pwl, g_pwl);
    #undef SYM

    const int SM128 = 2 * (128 + 128) * 72 * 2;   // 73728
    const int SM64  = 2 * (128 + 64)  * 72 * 2;   // 55296
    cudaFuncSetAttribute(mma_gemm<128,0,3>, cudaFuncAttributeMaxDynamicSharedMemorySize, SM128);
    cudaFuncSetAttribute(mma_gemm<128,1,3>, cudaFuncAttributeMaxDynamicSharedMemorySize, SM128);
    cudaFuncSetAttribute(mma_gemm<128,2,3>, cudaFuncAttributeMaxDynamicSharedMemorySize, SM128);
    cudaFuncSetAttribute(mma_gemm<64,2,2>,  cudaFuncAttributeMaxDynamicSharedMemorySize, SM64);

    // 1) conv + LN -> ynorm split
    conv_ln_kernel<<<B_*NYk, 256>>>(y, c1w, c1b, c2w, c2b, c3w, c3b, lnw, lnb);

    // 2) splits of x and weights
    split_kernel<<<3072, 256>>>(x,  (__nv_bfloat16*)xh,  (__nv_bfloat16*)xl,  786432);
    split_kernel<<<576,  256>>>(qw, (__nv_bfloat16*)qwh, (__nv_bfloat16*)qwl, 147456);
    split_kernel<<<1152, 256>>>(kvw,(__nv_bfloat16*)kvwh,(__nv_bfloat16*)kvwl,294912);
    split_kernel<<<576,  256>>>(pw, (__nv_bfloat16*)pwh, (__nv_bfloat16*)pwl, 147456);

    // 3) q = x @ q_w^T  -> split
    mma_gemm<128,2,3><<<dim3(6,32,1), 256, SM128>>>(
        (const __nv_bfloat16*)xh, (const __nv_bfloat16*)xl,
        (const __nv_bfloat16*)qwh, (const __nv_bfloat16*)qwl,
        nullptr, (__nv_bfloat16*)qh, (__nv_bfloat16*)ql, nullptr, nullptr,
        768, 768, 768, 768, 1.0f, 1, 0,0,0,0,0,0);

    // 4) kv = y_norm @ kv_w^T -> split
    mma_gemm<128,2,3><<<dim3(12,32,1), 256, SM128>>>(
        (const __nv_bfloat16*)ynh, (const __nv_bfloat16*)ynl,
        (const __nv_bfloat16*)kvwh, (const __nv_bfloat16*)kvwl,
        nullptr, (__nv_bfloat16*)kvh, (__nv_bfloat16*)kvl, nullptr, nullptr,
        768, 768, 768, 1536, 1.0f, 1, 0,0,0,0,0,0);

    // 5) V^T split
    vtrans_kernel<<<dim3(48,32), 256>>>();

    // 6) scores S = (q @ K^T) * D^-0.5  (48 heads)
    mma_gemm<128,0,3><<<dim3(8,8,48), 256, SM128>>>(
        (const __nv_bfloat16*)qh, (const __nv_bfloat16*)ql,
        (const __nv_bfloat16*)kvh, (const __nv_bfloat16*)kvl,
        (float*)S, nullptr, nullptr, nullptr, nullptr,
        64, 768, 1536, 1024, 0.125f, 12,
        (long long)1024*768, 64,
        (long long)1024*1536, 64,
        (long long)12*1024*1024, (long long)1024*1024);

    // 7) dual top-k -> combined weights W (bf16)
    select_kernel<<<dim3(1024, 48), 256>>>(pk1, pk2);

    // 8) attn = W @ V^T  -> split   (W single bf16, 2 segments)
    mma_gemm<64,2,2><<<dim3(1,8,48), 256, SM64>>>(
        (const __nv_bfloat16*)W, (const __nv_bfloat16*)W,
        (const __nv_bfloat16*)vth, (const __nv_bfloat16*)vtl,
        nullptr, (__nv_bfloat16*)ath, (__nv_bfloat16*)atl, nullptr, nullptr,
        1024, 1024, 1024, 768, 1.0f, 12,
        (long long)12*1024*1024, (long long)1024*1024,
        (long long)12*64*1024,   (long long)64*1024,
        (long long)1024*768, 64);

    // 9) out = attn @ proj_w^T + proj_b + x
    mma_gemm<128,1,3><<<dim3(6,32,1), 256, SM128>>>(
        (const __nv_bfloat16*)ath, (const __nv_bfloat16*)atl,
        (const __nv_bfloat16*)pwh, (const __nv_bfloat16*)pwl,
        out, nullptr, nullptr, pb, x,
        768, 768, 768, 768, 1.0f, 1, 0,0,0,0,0,0);
}

// round 5
// speedup vs baseline: 3.5984x; 1.4679x over previous
#include <cuda_runtime.h>
#include <cuda_bf16.h>
#include <cstdint>

#define B_  4
#define NXq 1024
#define NYk 1024
#define C_  768
#define H_  12
#define D_  64

// ======================= scratch (static device globals) =======================
__device__ float g_S[48u*1024u*1024u];                        // fp32 scores
__device__ __align__(16) __nv_bfloat16 g_x16 [B_*NXq*C_];
__device__ __align__(16) __nv_bfloat16 g_yn16[B_*NYk*C_];
__device__ __align__(16) __nv_bfloat16 g_q16 [B_*NXq*C_];
__device__ __align__(16) __nv_bfloat16 g_kv16[B_*NYk*2*C_];
__device__ __align__(16) __nv_bfloat16 g_vt16[48*64*1024];
__device__ __align__(16) __nv_bfloat16 g_W   [48u*1024u*1024u];
__device__ __align__(16) __nv_bfloat16 g_at16[B_*NXq*C_];
__device__ __align__(16) __nv_bfloat16 g_qw16 [C_*C_];
__device__ __align__(16) __nv_bfloat16 g_kvw16[2*C_*C_];
__device__ __align__(16) __nv_bfloat16 g_pw16 [C_*C_];

__device__ __forceinline__ uint32_t smem_u32(const void* p) {
    uint32_t a;
    asm("{ .reg .u64 t; cvta.to.shared.u64 t, %1; cvt.u32.u64 %0, t; }" : "=r"(a) : "l"(p));
    return a;
}
__device__ __forceinline__ void cp16(uint32_t dst, const void* src) {
    asm volatile("cp.async.cg.shared.global [%0], [%1], 16;" :: "r"(dst), "l"(src));
}

// ======================= fused multiscale conv + LayerNorm -> bf16 =======================
__global__ void __launch_bounds__(256) conv_ln_kernel(
    const float* __restrict__ y,
    const float* __restrict__ c1w, const float* __restrict__ c1b,
    const float* __restrict__ c2w, const float* __restrict__ c2b,
    const float* __restrict__ c3w, const float* __restrict__ c3b,
    const float* __restrict__ lnw, const float* __restrict__ lnb)
{
    int row = blockIdx.x;
    int b  = row >> 10;
    int ny = row & 1023;
    const float* yb = y + (size_t)b * NYk * C_;
    int tid = threadIdx.x;

    float vals[3];
    float lsum = 0.f, lsq = 0.f;
    #pragma unroll
    for (int i = 0; i < 3; i++) {
        int c = tid + i * 256;
        float w7[7];
        #pragma unroll
        for (int j = 0; j < 7; j++) w7[j] = c3w[c*7 + j];
        #pragma unroll
        for (int j = 0; j < 5; j++) w7[j+1] += c2w[c*5 + j];
        #pragma unroll
        for (int j = 0; j < 3; j++) w7[j+2] += c1w[c*3 + j];
        float acc = c1b[c] + c2b[c] + c3b[c];
        #pragma unroll
        for (int j = 0; j < 7; j++) {
            int nn = ny + j - 3;
            if (nn >= 0 && nn < NYk) acc += w7[j] * yb[(size_t)nn * C_ + c];
        }
        vals[i] = acc; lsum += acc; lsq += acc * acc;
    }

    __shared__ float s1[256], s2[256];
    s1[tid] = lsum; s2[tid] = lsq;
    __syncthreads();
    for (int s = 128; s > 0; s >>= 1) {
        if (tid < s) { s1[tid] += s1[tid+s]; s2[tid] += s2[tid+s]; }
        __syncthreads();
    }
    float mean = s1[0] * (1.0f / C_);
    float var  = s2[0] * (1.0f / C_) - mean * mean;
    float rstd = rsqrtf(var + 1e-5f);

    size_t base = (size_t)row * C_;
    #pragma unroll
    for (int i = 0; i < 3; i++) {
        int c = tid + i * 256;
        float v = (vals[i] - mean) * rstd * lnw[c] + lnb[c];
        g_yn16[base + c] = __float2bfloat16(v);
    }
}

// ======================= fp32 -> bf16 convert =======================
__global__ void __launch_bounds__(256) cvt_kernel(const float* __restrict__ s,
                                                  __nv_bfloat16* __restrict__ o,
                                                  int n4)
{
    int i = blockIdx.x * 256 + threadIdx.x;
    if (i >= n4) return;
    float4 v = ((const float4*)s)[i];
    __nv_bfloat162* O = (__nv_bfloat162*)o;
    O[2*i]   = __halves2bfloat162(__float2bfloat16(v.x), __float2bfloat16(v.y));
    O[2*i+1] = __halves2bfloat162(__float2bfloat16(v.z), __float2bfloat16(v.w));
}

// ======================= V transpose (bf16 -> transposed bf16) =======================
__global__ void __launch_bounds__(256) vtrans_kernel()
{
    int z  = blockIdx.x;        // 0..47 = b*12+h
    int t0 = blockIdx.y * 32;   // token tile
    int b = z / 12, h = z - b*12;
    __shared__ __nv_bfloat16 sh[64][33];
    int tid = threadIdx.x;
    #pragma unroll
    for (int i = 0; i < 8; i++) {
        int idx = tid + i*256;
        int tok = idx >> 6, d = idx & 63;
        size_t off = ((size_t)(b*1024 + t0 + tok)) * 1536 + 768 + h*64 + d;
        sh[d][tok] = g_kv16[off];
    }
    __syncthreads();
    #pragma unroll
    for (int i = 0; i < 8; i++) {
        int o = tid + i*256;
        int d = o >> 5, c = o & 31;
        size_t off = (size_t)z * 64 * 1024 + (size_t)d * 1024 + t0 + c;
        g_vt16[off] = sh[d][c];
    }
}

// ======================= HMMA GEMM: C = alpha * A @ B^T  (bf16 in, fp32 accum) =======================
// cp.async double-buffered, ldmatrix fragments. Tile 128 x NT, 8 warps.
// OUTM: 0 = fp32*alpha; 1 = fp32*alpha+bias+res; 2 = bf16 out.
template<int NT, int OUTM>
__global__ void __launch_bounds__(256) mma_gemm(
    const __nv_bfloat16* __restrict__ A, const __nv_bfloat16* __restrict__ B,
    float* __restrict__ Co, __nv_bfloat16* __restrict__ Cb,
    const float* __restrict__ bias, const float* __restrict__ res,
    int K, int lda, int ldb, int ldc, float alpha, int HH,
    long long aO, long long aI, long long bO, long long bI,
    long long cO, long long cI)
{
    constexpr int WM  = (NT == 128) ? 2 : 4;
    constexpr int WN  = 8 / WM;
    constexpr int WTM = 128 / WM;
    constexpr int WTN = NT / WN;
    constexpr int MT  = WTM / 16;
    constexpr int NTT = WTN / 8;
    constexpr int PITCH = 72;
    constexpr int ABYTES = 128 * PITCH * 2;
    constexpr int BBYTES = NT  * PITCH * 2;
    constexpr int STAGE  = ABYTES + BBYTES;

    extern __shared__ __align__(16) char dsm[];
    uint32_t smbase = smem_u32(dsm);

    int tid = threadIdx.x, wid = tid >> 5, lane = tid & 31;
    int wm = wid % WM, wn = wid / WM;

    int z = blockIdx.z, zo = z / HH, zi = z - zo * HH;
    A += zo*aO + zi*aI;
    B += zo*bO + zi*bI;
    long long coff = zo*cO + zi*cI;

    long long m0 = (long long)blockIdx.y * 128;
    long long n0 = (long long)blockIdx.x * NT;

    float acc[MT][NTT][4];
    #pragma unroll
    for (int i = 0; i < MT; i++)
        #pragma unroll
        for (int j = 0; j < NTT; j++)
            #pragma unroll
            for (int r = 0; r < 4; r++) acc[i][j][r] = 0.f;

    int nIter = K >> 6;

    uint32_t a_off = ((uint32_t)(wm*WTM + (lane & 15)) * PITCH + ((lane >> 4) << 3)) * 2;
    uint32_t b_off = ABYTES + ((uint32_t)(wn*WTN + (lane & 7)) * PITCH + (((lane >> 3) & 1) << 3)) * 2;

    auto issue = [&](int t) {
        int k0 = t << 6, s = t & 1;
        uint32_t sa = smbase + s * STAGE;
        uint32_t sb = sa + ABYTES;
        #pragma unroll
        for (int i = 0; i < 4; i++) {
            int ch = tid + (i << 8);
            int r = ch >> 3, c = (ch & 7) << 3;
            cp16(sa + (uint32_t)(r*PITCH + c)*2, A + (m0 + r)*lda + k0 + c);
        }
        #pragma unroll
        for (int i = 0; i < NT/32; i++) {
            int ch = tid + (i << 8);
            int r = ch >> 3, c = (ch & 7) << 3;
            cp16(sb + (uint32_t)(r*PITCH + c)*2, B + (n0 + r)*ldb + k0 + c);
        }
        asm volatile("cp.async.commit_group;");
    };

    issue(0);
    for (int t = 0; t < nIter; t++) {
        if (t + 1 < nIter) {
            issue(t + 1);
            asm volatile("cp.async.wait_group 1;");
        } else {
            asm volatile("cp.async.wait_group 0;");
        }
        __syncthreads();
        uint32_t stg = smbase + (uint32_t)(t & 1) * STAGE;
        uint32_t abase = stg + a_off;
        uint32_t bbase = stg + b_off;

        #pragma unroll
        for (int ks = 0; ks < 4; ks++) {
            uint32_t kb = (uint32_t)ks << 5;
            uint32_t af[MT][4];
            #pragma unroll
            for (int mt = 0; mt < MT; mt++) {
                asm volatile("ldmatrix.sync.aligned.m8n8.x4.shared.b16 {%0,%1,%2,%3}, [%4];"
                    : "=r"(af[mt][0]), "=r"(af[mt][1]), "=r"(af[mt][2]), "=r"(af[mt][3])
                    : "r"(abase + (uint32_t)(mt*16*PITCH*2) + kb));
            }
            uint32_t bf[NTT][2];
            #pragma unroll
            for (int nt = 0; nt < NTT; nt++) {
                asm volatile("ldmatrix.sync.aligned.m8n8.x2.shared.b16 {%0,%1}, [%2];"
                    : "=r"(bf[nt][0]), "=r"(bf[nt][1])
                    : "r"(bbase + (uint32_t)(nt*8*PITCH*2) + kb));
            }
            #pragma unroll
            for (int mt = 0; mt < MT; mt++)
                #pragma unroll
                for (int nt = 0; nt < NTT; nt++) {
                    asm volatile(
                        "mma.sync.aligned.m16n8k16.row.col.f32.bf16.bf16.f32 "
                        "{%0,%1,%2,%3}, {%4,%5,%6,%7}, {%8,%9}, {%0,%1,%2,%3};"
                        : "+f"(acc[mt][nt][0]), "+f"(acc[mt][nt][1]),
                          "+f"(acc[mt][nt][2]), "+f"(acc[mt][nt][3])
                        : "r"(af[mt][0]), "r"(af[mt][1]), "r"(af[mt][2]), "r"(af[mt][3]),
                          "r"(bf[nt][0]), "r"(bf[nt][1]));
                }
        }
        __syncthreads();
    }

    int gg = lane >> 2, qq = lane & 3;
    #pragma unroll
    for (int mt = 0; mt < MT; mt++) {
        long long gm = m0 + wm*WTM + mt*16 + gg;
        #pragma unroll
        for (int nt = 0; nt < NTT; nt++) {
            long long gn = n0 + wn*WTN + nt*8 + 2*qq;
            float v0 = acc[mt][nt][0] * alpha;
            float v1 = acc[mt][nt][1] * alpha;
            float v2 = acc[mt][nt][2] * alpha;
            float v3 = acc[mt][nt][3] * alpha;
            long long gi0 = coff + gm * (long long)ldc + gn;
            long long gi1 = gi0 + 8LL * ldc;
            if (OUTM == 0) {
                *(float2*)&Co[gi0] = make_float2(v0, v1);
                *(float2*)&Co[gi1] = make_float2(v2, v3);
            } else if (OUTM == 1) {
                float b0 = bias[gn], b1 = bias[gn + 1];
                float2 r0 = *(const float2*)&res[gi0];
                float2 r1 = *(const float2*)&res[gi1];
                *(float2*)&Co[gi0] = make_float2(v0 + b0 + r0.x, v1 + b1 + r0.y);
                *(float2*)&Co[gi1] = make_float2(v2 + b0 + r1.x, v3 + b1 + r1.y);
            } else {
                *(__nv_bfloat162*)&Cb[gi0] =
                    __halves2bfloat162(__float2bfloat16(v0), __float2bfloat16(v1));
                *(__nv_bfloat162*)&Cb[gi1] =
                    __halves2bfloat162(__float2bfloat16(v2), __float2bfloat16(v3));
            }
        }
    }
}

// ======================= dual top-k select -> combined softmax weights (bf16) =======================
__global__ void __launch_bounds__(256) select_kernel(const int* __restrict__ pk1,
                                                     const int* __restrict__ pk2)
{
    long long row = (long long)blockIdx.y * gridDim.x + blockIdx.x;
    const float4* Srow = (const float4*)(g_S + row * 1024);

    __shared__ unsigned hist[512];
    __shared__ unsigned warr[16];
    __shared__ float    fred[16];
    __shared__ unsigned s_p[2];
    __shared__ int      s_k[2];
    __shared__ float    s_m, s_z1, s_z2;

    int tid = threadIdx.x, lane = tid & 31, wid = tid >> 5;

    float4 vv = Srow[tid];
    float v[4] = {vv.x, vv.y, vv.z, vv.w};
    unsigned u[4];
    float mx = -3.4e38f;
    #pragma unroll
    for (int i = 0; i < 4; i++) {
        unsigned b = __float_as_uint(v[i]);
        u[i] = (b & 0x80000000u) ? ~b : (b | 0x80000000u);
        mx = fmaxf(mx, v[i]);
    }
    #pragma unroll
    for (int d = 16; d > 0; d >>= 1) mx = fmaxf(mx, __shfl_xor_sync(0xFFFFFFFFu, mx, d));
    if (lane == 0) fred[wid] = mx;

    int k1 = *pk1, k2 = *pk2;

    hist[tid] = 0u; hist[tid + 256] = 0u;
    __syncthreads();
    if (tid == 0) {
        float m = fred[0];
        #pragma unroll
        for (int w = 1; w < 8; w++) m = fmaxf(m, fred[w]);
        s_m = m;
    }
    #pragma unroll
    for (int i = 0; i < 4; i++) atomicAdd(&hist[u[i] >> 24], 1u);
    __syncthreads();
    {
        unsigned cnt = hist[tid];
        unsigned s = cnt;
        #pragma unroll
        for (int d = 1; d < 32; d <<= 1) {
            unsigned t = __shfl_down_sync(0xFFFFFFFFu, s, d);
            if (lane + d < 32) s += t;
        }
        if (lane == 0) warr[wid] = s;
        __syncthreads();
        unsigned cross = 0;
        #pragma unroll
        for (int w = 0; w < 8; w++) if (w > wid) cross += warr[w];
        unsigned here = s + cross, nxt = here - cnt;
        if (here >= (unsigned)k1 && nxt < (unsigned)k1) { s_p[0] = (unsigned)tid << 24; s_k[0] = k1 - (int)nxt; }
        if (here >= (unsigned)k2 && nxt < (unsigned)k2) { s_p[1] = (unsigned)tid << 24; s_k[1] = k2 - (int)nxt; }
    }
    __syncthreads();

    #pragma unroll
    for (int lev = 2; lev >= 0; lev--) {
        int sh = lev * 8;
        unsigned p1 = s_p[0], p2 = s_p[1];
        int kk1 = s_k[0], kk2 = s_k[1];
        bool same = (p1 == p2);
        unsigned himask = 0xFFFFFFFFu << (sh + 8);
        __syncthreads();
        hist[tid] = 0u; hist[tid + 256] = 0u;
        __syncthreads();
        #pragma unroll
        for (int i = 0; i < 4; i++) {
            unsigned uu = u[i];
            if (((uu ^ p1) & himask) == 0u) atomicAdd(&hist[(uu >> sh) & 255u], 1u);
            if (!same && ((uu ^ p2) & himask) == 0u) atomicAdd(&hist[256 + ((uu >> sh) & 255u)], 1u);
        }
        __syncthreads();
        {
            unsigned cnt1 = hist[tid];
            unsigned cnt2 = same ? cnt1 : hist[tid + 256];
            unsigned s1 = cnt1, s2 = cnt2;
            #pragma unroll
            for (int d = 1; d < 32; d <<= 1) {
                unsigned t1 = __shfl_down_sync(0xFFFFFFFFu, s1, d);
                unsigned t2 = __shfl_down_sync(0xFFFFFFFFu, s2, d);
                if (lane + d < 32) { s1 += t1; s2 += t2; }
            }
            if (lane == 0) { warr[wid] = s1; warr[8 + wid] = s2; }
            __syncthreads();
            unsigned cr1 = 0, cr2 = 0;
            #pragma unroll
            for (int w = 0; w < 8; w++) if (w > wid) { cr1 += warr[w]; cr2 += warr[8 + w]; }
            unsigned here1 = s1 + cr1, nxt1 = here1 - cnt1;
            unsigned here2 = s2 + cr2, nxt2 = here2 - cnt2;
            if (here1 >= (unsigned)kk1 && nxt1 < (unsigned)kk1) { s_p[0] = p1 | ((unsigned)tid << sh); s_k[0] = kk1 - (int)nxt1; }
            if (here2 >= (unsigned)kk2 && nxt2 < (unsigned)kk2) { s_p[1] = p2 | ((unsigned)tid << sh); s_k[1] = kk2 - (int)nxt2; }
        }
        __syncthreads();
    }

    unsigned t1 = s_p[0], t2 = s_p[1];
    float m = s_m;
    float e[4];
    float z1 = 0.f, z2 = 0.f;
    #pragma unroll
    for (int i = 0; i < 4; i++) {
        e[i] = __expf(v[i] - m);
        if (u[i] >= t1) z1 += e[i];
        if (u[i] >= t2) z2 += e[i];
    }
    #pragma unroll
    for (int d = 16; d > 0; d >>= 1) {
        z1 += __shfl_xor_sync(0xFFFFFFFFu, z1, d);
        z2 += __shfl_xor_sync(0xFFFFFFFFu, z2, d);
    }
    if (lane == 0) { fred[wid] = z1; fred[8 + wid] = z2; }
    __syncthreads();
    if (tid == 0) {
        float a = 0.f, b = 0.f;
        #pragma unroll
        for (int w = 0; w < 8; w++) { a += fred[w]; b += fred[8 + w]; }
        s_z1 = a; s_z2 = b;
    }
    __syncthreads();
    float c1 = 0.6f / s_z1;
    float c2 = 0.4f / s_z2;

    __nv_bfloat162* Wo = (__nv_bfloat162*)(g_W + row * 1024) + tid * 2;
    float w[4];
    #pragma unroll
    for (int i = 0; i < 4; i++)
        w[i] = e[i] * ((u[i] >= t1) ? c1 : 0.f) + e[i] * ((u[i] >= t2) ? c2 : 0.f);
    Wo[0] = __halves2bfloat162(__float2bfloat16(w[0]), __float2bfloat16(w[1]));
    Wo[1] = __halves2bfloat162(__float2bfloat16(w[2]), __float2bfloat16(w[3]));
}

// ======================= launch =======================
extern "C" void kernel_launch(void* const* d_in, const int* in_sizes, int n_in,
                              void* d_out, int out_size)
{
    const float* x   = (const float*)d_in[0];
    const float* y   = (const float*)d_in[1];
    const float* c1w = (const float*)d_in[2];
    const float* c1b = (const float*)d_in[3];
    const float* c2w = (const float*)d_in[4];
    const float* c2b = (const float*)d_in[5];
    const float* c3w = (const float*)d_in[6];
    const float* c3b = (const float*)d_in[7];
    const float* lnw = (const float*)d_in[8];
    const float* lnb = (const float*)d_in[9];
    const float* qw  = (const float*)d_in[10];
    const float* kvw = (const float*)d_in[11];
    const float* pw  = (const float*)d_in[12];
    const float* pb  = (const float*)d_in[13];
    const int*   pk1 = (const int*)d_in[14];
    const int*   pk2 = (const int*)d_in[15];
    float* out = (float*)d_out;

    #define SYM(p, g) void* p; cudaGetSymbolAddress(&p, g)
    SYM(S, g_S);
    SYM(x16, g_x16);   SYM(yn16, g_yn16);
    SYM(q16, g_q16);   SYM(kv16, g_kv16);
    SYM(vt16, g_vt16); SYM(W, g_W);
    SYM(at16, g_at16);
    SYM(qw16, g_qw16); SYM(kvw16, g_kvw16); SYM(pw16, g_pw16);
    #undef SYM

    const int SM128 = 2 * (128 + 128) * 72 * 2;   // 73728
    const int SM64  = 2 * (128 + 64)  * 72 * 2;   // 55296
    cudaFuncSetAttribute(mma_gemm<128,0>, cudaFuncAttributeMaxDynamicSharedMemorySize, SM128);
    cudaFuncSetAttribute(mma_gemm<128,1>, cudaFuncAttributeMaxDynamicSharedMemorySize, SM128);
    cudaFuncSetAttribute(mma_gemm<128,2>, cudaFuncAttributeMaxDynamicSharedMemorySize, SM128);
    cudaFuncSetAttribute(mma_gemm<64,2>,  cudaFuncAttributeMaxDynamicSharedMemorySize, SM64);

    // 1) conv + LN -> ynorm bf16
    conv_ln_kernel<<<B_*NYk, 256>>>(y, c1w, c1b, c2w, c2b, c3w, c3b, lnw, lnb);

    // 2) bf16 conversions of x and weights
    cvt_kernel<<<3072, 256>>>(x,  (__nv_bfloat16*)x16,  786432);
    cvt_kernel<<<576,  256>>>(qw, (__nv_bfloat16*)qw16, 147456);
    cvt_kernel<<<1152, 256>>>(kvw,(__nv_bfloat16*)kvw16,294912);
    cvt_kernel<<<576,  256>>>(pw, (__nv_bfloat16*)pw16, 147456);

    // 3) q = x @ q_w^T  -> bf16
    mma_gemm<128,2><<<dim3(6,32,1), 256, SM128>>>(
        (const __nv_bfloat16*)x16, (const __nv_bfloat16*)qw16,
        nullptr, (__nv_bfloat16*)q16, nullptr, nullptr,
        768, 768, 768, 768, 1.0f, 1, 0,0,0,0,0,0);

    // 4) kv = y_norm @ kv_w^T -> bf16
    mma_gemm<128,2><<<dim3(12,32,1), 256, SM128>>>(
        (const __nv_bfloat16*)yn16, (const __nv_bfloat16*)kvw16,
        nullptr, (__nv_bfloat16*)kv16, nullptr, nullptr,
        768, 768, 768, 1536, 1.0f, 1, 0,0,0,0,0,0);

    // 5) V^T
    vtrans_kernel<<<dim3(48,32), 256>>>();

    // 6) scores S = (q @ K^T) * D^-0.5  (48 heads) -> fp32
    mma_gemm<128,0><<<dim3(8,8,48), 256, SM128>>>(
        (const __nv_bfloat16*)q16, (const __nv_bfloat16*)kv16,
        (float*)S, nullptr, nullptr, nullptr,
        64, 768, 1536, 1024, 0.125f, 12,
        (long long)1024*768, 64,
        (long long)1024*1536, 64,
        (long long)12*1024*1024, (long long)1024*1024);

    // 7) dual top-k -> combined weights W (bf16)
    select_kernel<<<dim3(1024, 48), 256>>>(pk1, pk2);

    // 8) attn = W @ V^T -> bf16
    mma_gemm<64,2><<<dim3(1,8,48), 256, SM64>>>(
        (const __nv_bfloat16*)W, (const __nv_bfloat16*)vt16,
        nullptr, (__nv_bfloat16*)at16, nullptr, nullptr,
        1024, 1024, 1024, 768, 1.0f, 12,
        (long long)12*1024*1024, (long long)1024*1024,
        (long long)12*64*1024,   (long long)64*1024,
        (long long)1024*768, 64);

    // 9) out = attn @ proj_w^T + proj_b + x
    mma_gemm<128,1><<<dim3(6,32,1), 256, SM128>>>(
        (const __nv_bfloat16*)at16, (const __nv_bfloat16*)pw16,
        out, nullptr, pb, x,
        768, 768, 768, 768, 1.0f, 1, 0,0,0,0,0,0);
}